// round 1
// baseline (speedup 1.0000x reference)
#include <cuda_runtime.h>
#include <math.h>

#define LEAK 0.01f

// Shapes (fixed by the problem)
//  B=1024, H=512, half=256
//  c1: 2 -> 64, 3x3 s1 p1, 32x32
//  c2: 64 -> 128, 3x3 s2 p1, -> 16x16
//  c3: 128 -> 256, 16x16 kernel -> 1x1
//  GRU: H=512, gates 3*512

// ---------------- static scratch (no allocations allowed) ----------------
__device__ float g_c1[1024 * 64 * 32 * 32];   // 256 MB, [img][oc][32*32]
__device__ float g_c2[1024 * 128 * 16 * 16];  // 128 MB, [img][oc][16*16]
__device__ float g_x [1024 * 512];            // concat(pre_vec, height_vec)
__device__ float g_c3p[8 * 1024 * 256];       // split-K partials for c3
__device__ float g_gi[1024 * 3 * 512];
__device__ float g_gh[1024 * 3 * 512];

// ---------------- prebox linear: x[:, :256] ----------------
__global__ void k_prebox(const float* __restrict__ pb,
                         const float* __restrict__ w,
                         const float* __restrict__ bias) {
    int idx = blockIdx.x * 256 + threadIdx.x;     // 1024*256
    int b = idx >> 8, o = idx & 255;
    float acc = bias[o];
    acc = fmaf(pb[b * 3 + 0], w[o * 3 + 0], acc);
    acc = fmaf(pb[b * 3 + 1], w[o * 3 + 1], acc);
    acc = fmaf(pb[b * 3 + 2], w[o * 3 + 2], acc);
    g_x[b * 512 + o] = acc;
}

// ---------------- c1: direct conv, one CTA per image ----------------
__global__ __launch_bounds__(256) void k_c1(const float* __restrict__ hm,
                                            const float* __restrict__ w,
                                            const float* __restrict__ bias) {
    __shared__ float in_s[2 * 34 * 34];   // padded input
    __shared__ float w_s[64 * 18];
    __shared__ float b_s[64];
    int img = blockIdx.x, tid = threadIdx.x;

    for (int i = tid; i < 2 * 34 * 34; i += 256) in_s[i] = 0.f;
    __syncthreads();
    for (int i = tid; i < 2048; i += 256) {
        int ic = i >> 10, p = i & 1023, y = p >> 5, x = p & 31;
        in_s[ic * 1156 + (y + 1) * 34 + (x + 1)] = hm[img * 2048 + i];
    }
    for (int i = tid; i < 1152; i += 256) w_s[i] = w[i];
    if (tid < 64) b_s[tid] = bias[tid];
    __syncthreads();

    // 4 pixels per thread, inputs cached in registers
    float r[4][18];
#pragma unroll
    for (int g = 0; g < 4; g++) {
        int p = tid + 256 * g;
        int y = p >> 5, x = p & 31;
#pragma unroll
        for (int ic = 0; ic < 2; ic++)
#pragma unroll
            for (int kh = 0; kh < 3; kh++)
#pragma unroll
                for (int kw = 0; kw < 3; kw++)
                    r[g][ic * 9 + kh * 3 + kw] =
                        in_s[ic * 1156 + (y + kh) * 34 + (x + kw)];
    }

    for (int oc = 0; oc < 64; oc++) {
        float wr[18];
#pragma unroll
        for (int k = 0; k < 18; k++) wr[k] = w_s[oc * 18 + k];
        float bb = b_s[oc];
#pragma unroll
        for (int g = 0; g < 4; g++) {
            float acc = bb;
#pragma unroll
            for (int k = 0; k < 18; k++) acc = fmaf(r[g][k], wr[k], acc);
            acc = acc >= 0.f ? acc : LEAK * acc;
            g_c1[(img * 64 + oc) * 1024 + tid + 256 * g] = acc;
        }
    }
}

// ---------------- c2: stride-2 conv, CTA = (image, 32-oc block) ----------------
// 256 threads = 8 oc-groups x 32 pixel-threads; each thread: 4 oc x 8 pixels.
__global__ __launch_bounds__(256) void k_c2(const float* __restrict__ w,
                                            const float* __restrict__ bias) {
    __shared__ float in_s[8 * 34 * 34];   // 8 ic chunk, padded
    __shared__ float w_s[32 * 72];        // 32 oc x (8 ic * 9)
    int img = blockIdx.y, ocb = blockIdx.x;
    int tid = threadIdx.x;
    int px  = tid & 31;       // pixel-thread
    int oct = tid >> 5;       // oc-group 0..7
    int col = px & 15;        // output col
    int r0  = px >> 4;        // output row base (rows r0 + 2j)

    float acc[4][8];
#pragma unroll
    for (int i = 0; i < 4; i++)
#pragma unroll
        for (int j = 0; j < 8; j++) acc[i][j] = 0.f;

    for (int i = tid; i < 8 * 34 * 34; i += 256) in_s[i] = 0.f;  // borders

    for (int c = 0; c < 8; c++) {
        __syncthreads();
        for (int i = tid; i < 8192; i += 256) {
            int ic8 = i >> 10, p = i & 1023, y = p >> 5, x = p & 31;
            in_s[ic8 * 1156 + (y + 1) * 34 + (x + 1)] =
                g_c1[(img * 64 + c * 8 + ic8) * 1024 + p];
        }
        for (int i = tid; i < 2304; i += 256) {
            int ocl = i / 72, rem = i - ocl * 72;
            w_s[i] = w[(ocb * 32 + ocl) * 576 + c * 72 + rem];
        }
        __syncthreads();

        for (int ic8 = 0; ic8 < 8; ic8++) {
            const float* ibase = &in_s[ic8 * 1156];
            const float* wbase = &w_s[oct * 4 * 72 + ic8 * 9];
#pragma unroll
            for (int kh = 0; kh < 3; kh++) {
#pragma unroll
                for (int kw = 0; kw < 3; kw++) {
                    float wv[4];
#pragma unroll
                    for (int i = 0; i < 4; i++)
                        wv[i] = wbase[i * 72 + kh * 3 + kw];   // warp-broadcast
                    const float* ip = ibase + (2 * r0 + kh) * 34 + (2 * col + kw);
#pragma unroll
                    for (int j = 0; j < 8; j++) {
                        float iv = ip[j * 4 * 34];
#pragma unroll
                        for (int i = 0; i < 4; i++)
                            acc[i][j] = fmaf(wv[i], iv, acc[i][j]);
                    }
                }
            }
        }
    }

#pragma unroll
    for (int i = 0; i < 4; i++) {
        int oc = ocb * 32 + oct * 4 + i;
        float bb = bias[oc];
#pragma unroll
        for (int j = 0; j < 8; j++) {
            float v = acc[i][j] + bb;
            v = v >= 0.f ? v : LEAK * v;
            g_c2[(img * 128 + oc) * 256 + px + 32 * j] = v;
        }
    }
}

// ---------------- generic 64x64 SGEMM: C[m][n] = sum_k A[m][k]*B[n][k] ------
// grid: (N/64, M/64, splits). Each z-split covers kLen of K and writes its own
// partial block at C + z*cSplitStride (deterministic, no atomics).
__global__ __launch_bounds__(256) void k_gemm64(
    const float* __restrict__ A, int lda,
    const float* __restrict__ Bm, int ldb,
    float* __restrict__ C, int ldc,
    int kLen, long cSplitStride) {
    __shared__ __align__(16) float As[16 * 68];
    __shared__ __align__(16) float Bs[16 * 68];

    int tid = threadIdx.x;
    long m0 = blockIdx.y * 64, n0 = blockIdx.x * 64;
    long kStart = (long)blockIdx.z * kLen;
    C += (long)blockIdx.z * cSplitStride;

    int tx = tid & 15, ty = tid >> 4;       // 16 x 16 thread grid
    int lrow = tid >> 2;                    // 0..63
    int lk4  = (tid & 3) * 4;               // 0,4,8,12

    const float* Ap = A + (m0 + lrow) * lda + kStart + lk4;
    const float* Bp = Bm + (n0 + lrow) * ldb + kStart + lk4;

    float acc[4][4];
#pragma unroll
    for (int i = 0; i < 4; i++)
#pragma unroll
        for (int j = 0; j < 4; j++) acc[i][j] = 0.f;

    for (int kk = 0; kk < kLen; kk += 16) {
        float4 av = *(const float4*)(Ap + kk);
        float4 bv = *(const float4*)(Bp + kk);
        __syncthreads();
        As[(lk4 + 0) * 68 + lrow] = av.x;
        As[(lk4 + 1) * 68 + lrow] = av.y;
        As[(lk4 + 2) * 68 + lrow] = av.z;
        As[(lk4 + 3) * 68 + lrow] = av.w;
        Bs[(lk4 + 0) * 68 + lrow] = bv.x;
        Bs[(lk4 + 1) * 68 + lrow] = bv.y;
        Bs[(lk4 + 2) * 68 + lrow] = bv.z;
        Bs[(lk4 + 3) * 68 + lrow] = bv.w;
        __syncthreads();
#pragma unroll
        for (int k = 0; k < 16; k++) {
            float4 a = *(const float4*)&As[k * 68 + ty * 4];
            float4 b = *(const float4*)&Bs[k * 68 + tx * 4];
            acc[0][0] = fmaf(a.x, b.x, acc[0][0]);
            acc[0][1] = fmaf(a.x, b.y, acc[0][1]);
            acc[0][2] = fmaf(a.x, b.z, acc[0][2]);
            acc[0][3] = fmaf(a.x, b.w, acc[0][3]);
            acc[1][0] = fmaf(a.y, b.x, acc[1][0]);
            acc[1][1] = fmaf(a.y, b.y, acc[1][1]);
            acc[1][2] = fmaf(a.y, b.z, acc[1][2]);
            acc[1][3] = fmaf(a.y, b.w, acc[1][3]);
            acc[2][0] = fmaf(a.z, b.x, acc[2][0]);
            acc[2][1] = fmaf(a.z, b.y, acc[2][1]);
            acc[2][2] = fmaf(a.z, b.z, acc[2][2]);
            acc[2][3] = fmaf(a.z, b.w, acc[2][3]);
            acc[3][0] = fmaf(a.w, b.x, acc[3][0]);
            acc[3][1] = fmaf(a.w, b.y, acc[3][1]);
            acc[3][2] = fmaf(a.w, b.z, acc[3][2]);
            acc[3][3] = fmaf(a.w, b.w, acc[3][3]);
        }
    }

#pragma unroll
    for (int i = 0; i < 4; i++) {
        float4 v = make_float4(acc[i][0], acc[i][1], acc[i][2], acc[i][3]);
        *(float4*)&C[(m0 + ty * 4 + i) * ldc + n0 + tx * 4] = v;
    }
}

// ---------------- c3 split-K reduction + bias + leaky -> x[:, 256:] ---------
__global__ void k_c3red(const float* __restrict__ bias) {
    int idx = blockIdx.x * 256 + threadIdx.x;   // 1024*256
    int b = idx >> 8, o = idx & 255;
    float s = 0.f;
#pragma unroll
    for (int sp = 0; sp < 8; sp++) s += g_c3p[sp * (1024 * 256) + idx];
    s += bias[o];
    s = s >= 0.f ? s : LEAK * s;
    g_x[b * 512 + 256 + o] = s;
}

// ---------------- GRU gates + output ----------------
__global__ void k_gate(const float* __restrict__ h0,
                       const float* __restrict__ bih,
                       const float* __restrict__ bhh,
                       float* __restrict__ out) {
    int idx = blockIdx.x * 256 + threadIdx.x;   // 1024*512
    int b = idx >> 9, j = idx & 511;
    float ir = g_gi[b * 1536 + j]        + bih[j];
    float iz = g_gi[b * 1536 + 512 + j]  + bih[512 + j];
    float in = g_gi[b * 1536 + 1024 + j] + bih[1024 + j];
    float hr = g_gh[b * 1536 + j]        + bhh[j];
    float hz = g_gh[b * 1536 + 512 + j]  + bhh[512 + j];
    float hn = g_gh[b * 1536 + 1024 + j] + bhh[1024 + j];
    float r = 1.f / (1.f + expf(-(ir + hr)));
    float z = 1.f / (1.f + expf(-(iz + hz)));
    float n = tanhf(in + r * hn);
    float h = (1.f - z) * n + z * h0[idx];
    out[idx] = h;                 // rnn_out
    out[1024 * 512 + idx] = h;    // new_hh
}

// ---------------- launch ----------------
extern "C" void kernel_launch(void* const* d_in, const int* in_sizes, int n_in,
                              void* d_out, int out_size) {
    const float* pre_box   = (const float*)d_in[0];
    const float* heightmap = (const float*)d_in[1];
    const float* last_hh   = (const float*)d_in[2];
    const float* prebox_w  = (const float*)d_in[3];
    const float* prebox_b  = (const float*)d_in[4];
    const float* c1_w      = (const float*)d_in[5];
    const float* c1_b      = (const float*)d_in[6];
    const float* c2_w      = (const float*)d_in[7];
    const float* c2_b      = (const float*)d_in[8];
    const float* c3_w      = (const float*)d_in[9];
    const float* c3_b      = (const float*)d_in[10];
    const float* w_ih      = (const float*)d_in[11];
    const float* w_hh      = (const float*)d_in[12];
    const float* b_ih      = (const float*)d_in[13];
    const float* b_hh      = (const float*)d_in[14];
    float* out = (float*)d_out;

    float *p_c2, *p_c3p, *p_x, *p_gi, *p_gh;
    cudaGetSymbolAddress((void**)&p_c2, g_c2);
    cudaGetSymbolAddress((void**)&p_c3p, g_c3p);
    cudaGetSymbolAddress((void**)&p_x, g_x);
    cudaGetSymbolAddress((void**)&p_gi, g_gi);
    cudaGetSymbolAddress((void**)&p_gh, g_gh);

    k_prebox<<<1024, 256>>>(pre_box, prebox_w, prebox_b);
    k_c1<<<1024, 256>>>(heightmap, c1_w, c1_b);
    k_c2<<<dim3(4, 1024), 256>>>(c2_w, c2_b);

    // c3: [1024,256] = c2_flat[1024,32768] * c3_w[256,32768]^T, split-K=8
    k_gemm64<<<dim3(4, 16, 8), 256>>>(p_c2, 32768, c3_w, 32768,
                                      p_c3p, 256, 4096, (long)1024 * 256);
    k_c3red<<<1024, 256>>>(c3_b);

    // GRU GEMMs: gi = x * w_ih^T, gh = h0 * w_hh^T  (M=1024,N=1536,K=512)
    k_gemm64<<<dim3(24, 16, 1), 256>>>(p_x, 512, w_ih, 512, p_gi, 1536, 512, 0);
    k_gemm64<<<dim3(24, 16, 1), 256>>>(last_hh, 512, w_hh, 512, p_gh, 1536, 512, 0);

    k_gate<<<2048, 256>>>(last_hh, b_ih, b_hh, out);
}

// round 5
// speedup vs baseline: 2.7144x; 2.7144x over previous
#include <cuda_runtime.h>
#include <cstdint>
#include <math.h>

#define LEAK 0.01f

// Shapes: B=1024, H=512, half=256
// c1: 2->64 3x3 s1 p1 (32x32); c2: 64->128 3x3 s2 p1 (->16x16); c3: 128x16x16->256
// GRU: H=512

// ---------------- static scratch ----------------
__device__ float g_c1 [1024L * 32 * 32 * 64];   // NHWC c1 out (tf32-rounded), 256MB
__device__ float g_c2 [1024L * 128 * 256];      // [img][oc][px] (rounded) = c3 A rows
__device__ float g_w2 [128 * 9 * 64];           // c2 weights [oc][tap][ic] (rounded)
__device__ float g_w3 [256L * 32768];           // c3 weights rounded
__device__ float g_wih[1536 * 512];             // rounded
__device__ float g_whh[1536 * 512];             // rounded
__device__ float g_h0 [1024 * 512];             // rounded last_hh
__device__ float g_x  [1024 * 512];             // concat(pre_vec, height_vec), rounded
__device__ float g_c3p[32L * 1024 * 256];       // c3 split-K partials [z][b][o]
__device__ float g_gi [1024 * 1536];
__device__ float g_gh [1024 * 1536];

// ---------------- helpers ----------------
__device__ __forceinline__ uint32_t smem_u32(const void* p) {
    uint32_t a;
    asm("{ .reg .u64 t; cvta.to.shared.u64 t, %1; cvt.u32.u64 %0, t; }" : "=r"(a) : "l"(p));
    return a;
}
__device__ __forceinline__ float rndtf32(float f) {
    uint32_t r;
    asm("cvt.rna.tf32.f32 %0, %1;" : "=r"(r) : "f"(f));
    return __uint_as_float(r);
}
__device__ __forceinline__ void mma_tf32(float* c, uint32_t a0, uint32_t a1,
                                         uint32_t a2, uint32_t a3,
                                         uint32_t b0, uint32_t b1) {
    asm volatile(
        "mma.sync.aligned.m16n8k8.row.col.f32.tf32.tf32.f32 "
        "{%0,%1,%2,%3}, {%4,%5,%6,%7}, {%8,%9}, {%0,%1,%2,%3};"
        : "+f"(c[0]), "+f"(c[1]), "+f"(c[2]), "+f"(c[3])
        : "r"(a0), "r"(a1), "r"(a2), "r"(a3), "r"(b0), "r"(b1));
}

// ---- shared GEMM core: BM=128 BN=128 BK=32, 8 warps (2M x 4N), warp 64x32 ----
// smem float4 layout per 128x32 tile: o4 = row*8 + (c4 ^ (row&7))
__device__ __forceinline__ void compute_stage(uint32_t aS, uint32_t bS, int lane,
                                              int wm, int wn,
                                              float (&acc)[4][4][4]) {
    int t = lane >> 3, r8 = lane & 7;
    int rowA = wm * 64 + (t & 1) * 8 + r8;
    int thA = t >> 1;
    int rowB = wn * 32 + (t >> 1) * 8 + r8;
    int thB = t & 1;
#pragma unroll
    for (int kk = 0; kk < 4; kk++) {
        uint32_t a[4][4];
#pragma unroll
        for (int mt = 0; mt < 4; mt++) {
            uint32_t adr = aS + (uint32_t)(((((rowA + mt * 16) << 3) +
                            ((kk * 2 + thA) ^ r8))) << 4);
            asm volatile("ldmatrix.sync.aligned.m8n8.x4.shared.b16 {%0,%1,%2,%3}, [%4];"
                         : "=r"(a[mt][0]), "=r"(a[mt][1]), "=r"(a[mt][2]), "=r"(a[mt][3])
                         : "r"(adr));
        }
        uint32_t b[4][2];
#pragma unroll
        for (int p = 0; p < 2; p++) {
            uint32_t adr = bS + (uint32_t)(((((rowB + p * 16) << 3) +
                            ((kk * 2 + thB) ^ r8))) << 4);
            uint32_t r0, r1, r2, r3;
            asm volatile("ldmatrix.sync.aligned.m8n8.x4.shared.b16 {%0,%1,%2,%3}, [%4];"
                         : "=r"(r0), "=r"(r1), "=r"(r2), "=r"(r3) : "r"(adr));
            b[p * 2][0] = r0; b[p * 2][1] = r1;
            b[p * 2 + 1][0] = r2; b[p * 2 + 1][1] = r3;
        }
#pragma unroll
        for (int mt = 0; mt < 4; mt++)
#pragma unroll
            for (int nt = 0; nt < 4; nt++)
                mma_tf32(acc[mt][nt], a[mt][0], a[mt][1], a[mt][2], a[mt][3],
                         b[nt][0], b[nt][1]);
    }
}

// ---------------- rounding copy ----------------
__global__ void k_round4(float4* __restrict__ dst, const float4* __restrict__ src, int n4) {
    int i = blockIdx.x * 256 + threadIdx.x;
    if (i < n4) {
        float4 v = src[i];
        v.x = rndtf32(v.x); v.y = rndtf32(v.y); v.z = rndtf32(v.z); v.w = rndtf32(v.w);
        dst[i] = v;
    }
}

// ---------------- prebox linear -> x[:, :256] ----------------
__global__ void k_prebox(const float* __restrict__ pb, const float* __restrict__ w,
                         const float* __restrict__ bias) {
    int idx = blockIdx.x * 256 + threadIdx.x;
    int b = idx >> 8, o = idx & 255;
    float acc = bias[o];
    acc = fmaf(pb[b * 3 + 0], w[o * 3 + 0], acc);
    acc = fmaf(pb[b * 3 + 1], w[o * 3 + 1], acc);
    acc = fmaf(pb[b * 3 + 2], w[o * 3 + 2], acc);
    g_x[b * 512 + o] = rndtf32(acc);
}

// ---------------- repack c2 weights [oc][ic][tap] -> [oc][tap][ic], rounded ----
__global__ void k_repack(const float* __restrict__ w) {
    int idx = blockIdx.x * 256 + threadIdx.x;   // 128*576
    int oc = idx / 576, rem = idx - oc * 576;
    int tap = rem >> 6, ic = rem & 63;
    g_w2[idx] = rndtf32(w[oc * 576 + ic * 9 + tap]);
}

// ---------------- c1: direct conv -> NHWC (rounded) ----------------
__global__ __launch_bounds__(256) void k_c1(const float* __restrict__ hm,
                                            const float* __restrict__ w,
                                            const float* __restrict__ bias) {
    __shared__ float in_s[2 * 34 * 34];
    __shared__ float w_s[64 * 18];
    __shared__ float b_s[64];
    int img = blockIdx.x, tid = threadIdx.x;

    for (int i = tid; i < 2 * 34 * 34; i += 256) in_s[i] = 0.f;
    __syncthreads();
    for (int i = tid; i < 2048; i += 256) {
        int ic = i >> 10, p = i & 1023, y = p >> 5, x = p & 31;
        in_s[ic * 1156 + (y + 1) * 34 + (x + 1)] = hm[img * 2048 + i];
    }
    for (int i = tid; i < 1152; i += 256) w_s[i] = w[i];
    if (tid < 64) b_s[tid] = bias[tid];
    __syncthreads();

#pragma unroll
    for (int g = 0; g < 4; g++) {
        int p = tid + 256 * g;
        int y = p >> 5, x = p & 31;
        float r[18];
#pragma unroll
        for (int ic = 0; ic < 2; ic++)
#pragma unroll
            for (int kh = 0; kh < 3; kh++)
#pragma unroll
                for (int kw = 0; kw < 3; kw++)
                    r[ic * 9 + kh * 3 + kw] = in_s[ic * 1156 + (y + kh) * 34 + (x + kw)];
        float4 v4[16];
        float* v = (float*)v4;
        for (int oc = 0; oc < 64; oc++) {
            float acc = b_s[oc];
#pragma unroll
            for (int k = 0; k < 18; k++) acc = fmaf(r[k], w_s[oc * 18 + k], acc);
            acc = acc >= 0.f ? acc : LEAK * acc;
            v[oc] = rndtf32(acc);
        }
        float4* dst = (float4*)&g_c1[((long)img * 1024 + p) * 64];
#pragma unroll
        for (int q = 0; q < 16; q++) dst[q] = v4[q];
    }
}

// ---------------- c2: implicit GEMM via mma.sync ----------------
// CTA = (img half: 128 px) x (128 oc). K = 18 stages of 32 (tap-major).
__global__ __launch_bounds__(256) void k_c2mma(const float* __restrict__ bias) {
    __shared__ float4 sm4[2048];   // 32KB: A tile [0,1024), B tile [1024,2048)
    int tid = threadIdx.x, lane = tid & 31, w = tid >> 5;
    int wm = w & 1, wn = w >> 1;
    int img = blockIdx.x >> 1, pxl = (blockIdx.x & 1) * 128;
    int rowL = tid >> 3, c4 = tid & 7;
    uint32_t smbase = smem_u32(sm4);

    float acc[4][4][4] = {};
    float4 ra[4], rb[4];

    auto ldg = [&](int c) {
        int t = c >> 1, h = c & 1;
        int ty = t / 3, tx = t - ty * 3;
#pragma unroll
        for (int i = 0; i < 4; i++) {
            int row = rowL + 32 * i;
            int px = pxl + row, oy = px >> 4, ox = px & 15;
            int iy = 2 * oy + ty - 1, ix = 2 * ox + tx - 1;
            if ((unsigned)iy < 32u && (unsigned)ix < 32u)
                ra[i] = *(const float4*)&g_c1[
                    (((long)img * 32 + iy) * 32 + ix) * 64 + h * 32 + c4 * 4];
            else
                ra[i] = make_float4(0.f, 0.f, 0.f, 0.f);
            rb[i] = *(const float4*)&g_w2[row * 576 + c * 32 + c4 * 4];
        }
    };
    auto sts = [&]() {
#pragma unroll
        for (int i = 0; i < 4; i++) {
            int row = rowL + 32 * i;
            int o4 = (row << 3) + (c4 ^ (row & 7));
            sm4[o4] = ra[i];
            sm4[1024 + o4] = rb[i];
        }
    };

    ldg(0); sts(); __syncthreads();
    for (int s = 0; s < 18; s++) {
        if (s + 1 < 18) ldg(s + 1);
        compute_stage(smbase, smbase + 16384, lane, wm, wn, acc);
        __syncthreads();
        if (s + 1 < 18) { sts(); __syncthreads(); }
    }

    int mr = lane >> 2, nc = (lane & 3) * 2;
#pragma unroll
    for (int mt = 0; mt < 4; mt++)
#pragma unroll
        for (int nt = 0; nt < 4; nt++) {
            int m = wm * 64 + mt * 16 + mr;       // pixel (local)
            int n = wn * 32 + nt * 8 + nc;        // oc
#pragma unroll
            for (int q = 0; q < 4; q++) {
                int mm = m + (q >> 1) * 8, oc = n + (q & 1);
                float v = acc[mt][nt][q] + __ldg(&bias[oc]);
                v = v >= 0.f ? v : LEAK * v;
                g_c2[(long)img * 32768 + (long)oc * 256 + (pxl + mm)] = rndtf32(v);
            }
        }
}

// ---------------- generic GEMM: C[M][N] = A[M,K] * B[N,K]^T ----------------
__global__ __launch_bounds__(256) void k_gemm_mma(
    const float* __restrict__ A, int lda,
    const float* __restrict__ B, int ldb,
    float* __restrict__ C, int ldc, int S, long cSplit) {
    __shared__ float4 sm4[2048];   // 32KB single buffer
    int tid = threadIdx.x, lane = tid & 31, w = tid >> 5;
    int wm = w & 1, wn = w >> 1;
    long m0 = blockIdx.y * 128, n0 = blockIdx.x * 128;
    long kBase = (long)blockIdx.z * S * 32;
    C += (long)blockIdx.z * cSplit;
    const float* Ap = A + m0 * lda + kBase;
    const float* Bp = B + n0 * ldb + kBase;
    int rowL = tid >> 3, c4 = tid & 7;
    uint32_t smbase = smem_u32(sm4);

    float acc[4][4][4] = {};
    float4 ra[4], rb[4];

    auto ldg = [&](int s) {
        long k0 = (long)s * 32 + c4 * 4;
#pragma unroll
        for (int i = 0; i < 4; i++) {
            long row = rowL + 32 * i;
            ra[i] = *(const float4*)(Ap + row * lda + k0);
            rb[i] = *(const float4*)(Bp + row * ldb + k0);
        }
    };
    auto sts = [&]() {
#pragma unroll
        for (int i = 0; i < 4; i++) {
            int row = rowL + 32 * i;
            int o4 = (row << 3) + (c4 ^ (row & 7));
            sm4[o4] = ra[i];
            sm4[1024 + o4] = rb[i];
        }
    };

    ldg(0); sts(); __syncthreads();
    for (int s = 0; s < S; s++) {
        if (s + 1 < S) ldg(s + 1);
        compute_stage(smbase, smbase + 16384, lane, wm, wn, acc);
        __syncthreads();
        if (s + 1 < S) { sts(); __syncthreads(); }
    }

    int mr = lane >> 2, nc = (lane & 3) * 2;
#pragma unroll
    for (int mt = 0; mt < 4; mt++)
#pragma unroll
        for (int nt = 0; nt < 4; nt++) {
            long m = m0 + wm * 64 + mt * 16 + mr;
            long n = n0 + wn * 32 + nt * 8 + nc;
            *(float2*)&C[m * ldc + n] = make_float2(acc[mt][nt][0], acc[mt][nt][1]);
            *(float2*)&C[(m + 8) * ldc + n] = make_float2(acc[mt][nt][2], acc[mt][nt][3]);
        }
}

// ---------------- c3 split-K reduce + bias + leaky -> x[:, 256:] (rounded) ----
__global__ void k_c3red(const float* __restrict__ bias) {
    int idx = blockIdx.x * 256 + threadIdx.x;   // 1024*256
    int b = idx >> 8, o = idx & 255;
    float s = 0.f;
#pragma unroll
    for (int sp = 0; sp < 32; sp++) s += g_c3p[(long)sp * 262144 + idx];
    s += bias[o];
    s = s >= 0.f ? s : LEAK * s;
    g_x[b * 512 + 256 + o] = rndtf32(s);
}

// ---------------- GRU gates + output ----------------
__global__ void k_gate(const float* __restrict__ h0,
                       const float* __restrict__ bih,
                       const float* __restrict__ bhh,
                       float* __restrict__ out) {
    int idx = blockIdx.x * 256 + threadIdx.x;   // 1024*512
    int b = idx >> 9, j = idx & 511;
    float ir = g_gi[b * 1536 + j]        + bih[j];
    float iz = g_gi[b * 1536 + 512 + j]  + bih[512 + j];
    float in = g_gi[b * 1536 + 1024 + j] + bih[1024 + j];
    float hr = g_gh[b * 1536 + j]        + bhh[j];
    float hz = g_gh[b * 1536 + 512 + j]  + bhh[512 + j];
    float hn = g_gh[b * 1536 + 1024 + j] + bhh[1024 + j];
    float r = 1.f / (1.f + expf(-(ir + hr)));
    float z = 1.f / (1.f + expf(-(iz + hz)));
    float n = tanhf(in + r * hn);
    float h = (1.f - z) * n + z * h0[idx];
    out[idx] = h;
    out[1024 * 512 + idx] = h;
}

// ---------------- launch ----------------
extern "C" void kernel_launch(void* const* d_in, const int* in_sizes, int n_in,
                              void* d_out, int out_size) {
    const float* pre_box   = (const float*)d_in[0];
    const float* heightmap = (const float*)d_in[1];
    const float* last_hh   = (const float*)d_in[2];
    const float* prebox_w  = (const float*)d_in[3];
    const float* prebox_b  = (const float*)d_in[4];
    const float* c1_w      = (const float*)d_in[5];
    const float* c1_b      = (const float*)d_in[6];
    const float* c2_w      = (const float*)d_in[7];
    const float* c2_b      = (const float*)d_in[8];
    const float* c3_w      = (const float*)d_in[9];
    const float* c3_b      = (const float*)d_in[10];
    const float* w_ih      = (const float*)d_in[11];
    const float* w_hh      = (const float*)d_in[12];
    const float* b_ih      = (const float*)d_in[13];
    const float* b_hh      = (const float*)d_in[14];
    float* out = (float*)d_out;

    float *p_c2, *p_c3p, *p_x, *p_gi, *p_gh, *p_w3, *p_wih, *p_whh, *p_h0;
    cudaGetSymbolAddress((void**)&p_c2, g_c2);
    cudaGetSymbolAddress((void**)&p_c3p, g_c3p);
    cudaGetSymbolAddress((void**)&p_x, g_x);
    cudaGetSymbolAddress((void**)&p_gi, g_gi);
    cudaGetSymbolAddress((void**)&p_gh, g_gh);
    cudaGetSymbolAddress((void**)&p_w3, g_w3);
    cudaGetSymbolAddress((void**)&p_wih, g_wih);
    cudaGetSymbolAddress((void**)&p_whh, g_whh);
    cudaGetSymbolAddress((void**)&p_h0, g_h0);

    // tf32-round weight/state copies
    k_round4<<<(8388608 / 4 + 255) / 256, 256>>>((float4*)p_w3, (const float4*)c3_w, 8388608 / 4);
    k_round4<<<(786432 / 4 + 255) / 256, 256>>>((float4*)p_wih, (const float4*)w_ih, 786432 / 4);
    k_round4<<<(786432 / 4 + 255) / 256, 256>>>((float4*)p_whh, (const float4*)w_hh, 786432 / 4);
    k_round4<<<(524288 / 4 + 255) / 256, 256>>>((float4*)p_h0, (const float4*)last_hh, 524288 / 4);

    k_prebox<<<1024, 256>>>(pre_box, prebox_w, prebox_b);
    k_repack<<<288, 256>>>(c2_w);
    k_c1<<<1024, 256>>>(heightmap, c1_w, c1_b);

    k_c2mma<<<2048, 256>>>(c2_b);

    // c3: M=1024, N=256, K=32768, split-K=32
    k_gemm_mma<<<dim3(2, 8, 32), 256>>>(p_c2, 32768, p_w3, 32768,
                                        p_c3p, 256, 32, 262144L);
    k_c3red<<<1024, 256>>>(c3_b);

    // GRU: gi = x*w_ih^T, gh = h0*w_hh^T  (M=1024, N=1536, K=512)
    k_gemm_mma<<<dim3(12, 8, 1), 256>>>(p_x, 512, p_wih, 512, p_gi, 1536, 16, 0);
    k_gemm_mma<<<dim3(12, 8, 1), 256>>>(p_h0, 512, p_whh, 512, p_gh, 1536, 16, 0);

    k_gate<<<2048, 256>>>(last_hh, b_ih, b_hh, out);
}